// round 3
// baseline (speedup 1.0000x reference)
#include <cuda_runtime.h>
#include <math.h>

// ---------------- problem constants ----------------
#define BB 16
#define TT 8
#define CIN 3
#define HW 196
#define HID 32
#define IND 16
#define KBIG 6272       // HID*HW
#define K0 588          // CIN*HW
#define K0PAD 640
#define NBU 3136        // IND*HW
#define NTD 9408        // (IND+HID)*HW
#define TK 512          // GEMM K tile
#define SROW 20         // smem row stride (floats) -> conflict-free LDS.128

// ---------------- device scratch (no allocs allowed) ----------------
__device__ float g_h[3 * 2 * BB * HID * HW];   // hidden, double buffered
__device__ float g_xT[TT * K0PAD * BB];        // transposed+padded input slices
__device__ float g_poolBU[KBIG * BB];
__device__ float g_poolTD[KBIG * BB];
__device__ float g_bu[BB * NBU];
__device__ float g_td[BB * NTD];
__device__ float g_gates[BB * 64 * HW];
__device__ float g_fc1o[BB * 100];

// ---------------- f32x2 helpers ----------------
__device__ __forceinline__ unsigned long long pack2(float v) {
    unsigned long long r;
    asm("mov.b64 %0, {%1, %1};" : "=l"(r) : "f"(v));
    return r;
}
__device__ __forceinline__ void fma2(unsigned long long& d, unsigned long long a,
                                     unsigned long long b) {
    asm("fma.rn.f32x2 %0, %1, %2, %0;" : "+l"(d) : "l"(a), "l"(b));
}
__device__ __forceinline__ unsigned long long add2(unsigned long long a,
                                                   unsigned long long b) {
    unsigned long long r;
    asm("add.rn.f32x2 %0, %1, %2;" : "=l"(r) : "l"(a), "l"(b));
    return r;
}

// ---------------- GEMM: out[b][n] = sum_k inT[k][b]*W[n][k] + bias[n] ----------------
// inT: (Krows, 16) row-major (padded rows must be zero beyond K)
// W:   (Nout, K) row-major;  out: (16, Nout)
// 128 threads = 4 warps, 4 rows per warp -> 16 rows/block
__global__ void __launch_bounds__(128) gemm_k(
    const float* __restrict__ inT, const float* __restrict__ W,
    const float* __restrict__ bias, float* __restrict__ out,
    int K, int Krows, int Nout)
{
    __shared__ float s[TK * SROW];   // 40KB
    const int tid  = threadIdx.x;
    const int warp = tid >> 5, lane = tid & 31;
    const int row0 = blockIdx.x * 16 + warp * 4;

    unsigned long long acc[4][8];
#pragma unroll
    for (int r = 0; r < 4; r++)
#pragma unroll
        for (int j = 0; j < 8; j++) acc[r][j] = 0ull;

    const int ntiles = (Krows + TK - 1) / TK;
    for (int t = 0; t < ntiles; t++) {
        __syncthreads();
        // cooperative tile load: (TK x 16) floats, stride-20 rows in smem
#pragma unroll
        for (int i = 0; i < 16; i++) {
            int f = tid + i * 128;       // float4 index 0..2047
            int k = f >> 2, q = f & 3;
            int kg = t * TK + k;
            float4 v = make_float4(0.f, 0.f, 0.f, 0.f);
            if (kg < Krows) v = ((const float4*)inT)[(size_t)kg * 4 + q];
            *(float4*)(s + k * SROW + q * 4) = v;
        }
        __syncthreads();
        const int kb = t * TK;
#pragma unroll 4
        for (int it = 0; it < TK / 32; ++it) {
            int kl = it * 32 + lane;
            int kg = kb + kl;
            float w0 = 0.f, w1 = 0.f, w2 = 0.f, w3 = 0.f;
            if (kg < K) {
                const float* wp = W + (size_t)row0 * K + kg;
                w0 = wp[0];
                w1 = wp[K];
                w2 = wp[(size_t)2 * K];
                w3 = wp[(size_t)3 * K];
            }
            const ulonglong2* ap = (const ulonglong2*)(s + kl * SROW);
            ulonglong2 u0 = ap[0], u1 = ap[1], u2 = ap[2], u3 = ap[3];
            unsigned long long av[8] = {u0.x, u0.y, u1.x, u1.y, u2.x, u2.y, u3.x, u3.y};
            unsigned long long W2[4] = {pack2(w0), pack2(w1), pack2(w2), pack2(w3)};
#pragma unroll
            for (int r = 0; r < 4; r++)
#pragma unroll
                for (int j = 0; j < 8; j++) fma2(acc[r][j], W2[r], av[j]);
        }
    }
    // cross-lane reduction (butterfly over 32 lanes)
#pragma unroll
    for (int off = 16; off; off >>= 1)
#pragma unroll
        for (int r = 0; r < 4; r++)
#pragma unroll
            for (int j = 0; j < 8; j++)
                acc[r][j] = add2(acc[r][j],
                                 __shfl_xor_sync(0xffffffffu, acc[r][j], off));
    if (lane < 16) {
        const int b = lane, j = b >> 1;
#pragma unroll
        for (int r = 0; r < 4; r++) {
            unsigned long long v = acc[r][j];
            float f = (b & 1) ? __uint_as_float((unsigned)(v >> 32))
                              : __uint_as_float((unsigned)v);
            int n = row0 + r;
            out[(size_t)b * Nout + n] = f + bias[n];
        }
    }
}

// ---------------- gate conv: comb=[bu,h](+td) -> conv3x3 (48->64) -> sigmoid ----------------
// grid (16 batches, 16 groups of 4 outch), 256 threads
__global__ void __launch_bounds__(256) gate_k(
    const float* __restrict__ bu, const float* __restrict__ h,
    const float* __restrict__ td, const float* __restrict__ Wg,
    const float* __restrict__ bg, float* __restrict__ gates, int has_td)
{
    extern __shared__ float sm[];
    float* sc = sm;                 // 48 * 256  (16x16 zero-haloed images)
    float* sw = sm + 48 * 256;      // 4 * 432
    const int b = blockIdx.x, grp = blockIdx.y;
    const int tid = threadIdx.x;
    for (int i = tid; i < 48 * 256; i += 256) sc[i] = 0.f;
    for (int i = tid; i < 1728; i += 256) sw[i] = Wg[grp * 1728 + i];
    __syncthreads();
    for (int i = tid; i < 48 * 196; i += 256) {
        int ic = i / 196, p = i - ic * 196, y = p / 14, x = p - y * 14;
        float v = (ic < IND) ? bu[((size_t)b * IND + ic) * 196 + p]
                             : h[((size_t)b * HID + (ic - IND)) * 196 + p];
        if (has_td) v += td[((size_t)b * 48 + ic) * 196 + p];
        sc[ic * 256 + (y + 1) * 16 + (x + 1)] = v;
    }
    __syncthreads();
    if (tid < 196) {
        const int p = tid, y = p / 14, x = p - y * 14;
        float a0 = bg[grp * 4 + 0], a1 = bg[grp * 4 + 1];
        float a2 = bg[grp * 4 + 2], a3 = bg[grp * 4 + 3];
        const float* cbase = sc + y * 16 + x;
        for (int ic = 0; ic < 48; ++ic) {
            float v[9];
            const float* cb = cbase + ic * 256;
#pragma unroll
            for (int dy = 0; dy < 3; dy++)
#pragma unroll
                for (int dx = 0; dx < 3; dx++) v[dy * 3 + dx] = cb[dy * 16 + dx];
            const float* w0 = sw + ic * 9;
#pragma unroll
            for (int q = 0; q < 9; q++) {
                a0 += w0[q] * v[q];
                a1 += w0[432 + q] * v[q];
                a2 += w0[864 + q] * v[q];
                a3 += w0[1296 + q] * v[q];
            }
        }
        float* gp = gates + ((size_t)b * 64 + grp * 4) * 196 + p;
        gp[0]   = 1.f / (1.f + expf(-a0));
        gp[196] = 1.f / (1.f + expf(-a1));
        gp[392] = 1.f / (1.f + expf(-a2));
        gp[588] = 1.f / (1.f + expf(-a3));
    }
}

// ---------------- cand conv + GRU update: comb2=[bu, r*h] -> conv (48->32) -> tanh
//                  h_new = (1-z)*h + z*cand  ----------------
// grid (16 batches, 8 groups of 4 outch), 256 threads
__global__ void __launch_bounds__(256) cand_k(
    const float* __restrict__ bu, const float* __restrict__ h,
    const float* __restrict__ gates, const float* __restrict__ Wc,
    const float* __restrict__ bc, float* __restrict__ hnew)
{
    extern __shared__ float sm[];
    float* sc = sm;
    float* sw = sm + 48 * 256;
    const int b = blockIdx.x, grp = blockIdx.y;
    const int tid = threadIdx.x;
    for (int i = tid; i < 48 * 256; i += 256) sc[i] = 0.f;
    for (int i = tid; i < 1728; i += 256) sw[i] = Wc[grp * 1728 + i];
    __syncthreads();
    for (int i = tid; i < 48 * 196; i += 256) {
        int ic = i / 196, p = i - ic * 196, y = p / 14, x = p - y * 14;
        float v;
        if (ic < IND) {
            v = bu[((size_t)b * IND + ic) * 196 + p];
        } else {
            int c = ic - IND;
            v = gates[((size_t)b * 64 + c) * 196 + p] *
                h[((size_t)b * HID + c) * 196 + p];
        }
        sc[ic * 256 + (y + 1) * 16 + (x + 1)] = v;
    }
    __syncthreads();
    if (tid < 196) {
        const int p = tid, y = p / 14, x = p - y * 14;
        float a0 = bc[grp * 4 + 0], a1 = bc[grp * 4 + 1];
        float a2 = bc[grp * 4 + 2], a3 = bc[grp * 4 + 3];
        const float* cbase = sc + y * 16 + x;
        for (int ic = 0; ic < 48; ++ic) {
            float v[9];
            const float* cb = cbase + ic * 256;
#pragma unroll
            for (int dy = 0; dy < 3; dy++)
#pragma unroll
                for (int dx = 0; dx < 3; dx++) v[dy * 3 + dx] = cb[dy * 16 + dx];
            const float* w0 = sw + ic * 9;
#pragma unroll
            for (int q = 0; q < 9; q++) {
                a0 += w0[q] * v[q];
                a1 += w0[432 + q] * v[q];
                a2 += w0[864 + q] * v[q];
                a3 += w0[1296 + q] * v[q];
            }
        }
        float a[4] = {a0, a1, a2, a3};
#pragma unroll
        for (int g = 0; g < 4; g++) {
            int oc = grp * 4 + g;
            float z  = gates[((size_t)b * 64 + 32 + oc) * 196 + p];
            float ho = h[((size_t)b * HID + oc) * 196 + p];
            hnew[((size_t)b * HID + oc) * 196 + p] = (1.f - z) * ho + z * tanhf(a[g]);
        }
    }
}

// ---------------- maxpool 3x3 s1 p1 + transpose to (K,16) ----------------
__global__ void pool_k(const float* __restrict__ h, float* __restrict__ outT) {
    int idx = blockIdx.x * 256 + threadIdx.x;
    if (idx >= BB * KBIG) return;
    int b = idx & 15, k = idx >> 4;
    int c = k / 196, p = k - c * 196, y = p / 14, x = p - y * 14;
    const float* hp = h + ((size_t)b * HID + c) * 196;
    int y0 = y > 0 ? y - 1 : 0, y1 = y < 13 ? y + 1 : 13;
    int x0 = x > 0 ? x - 1 : 0, x1 = x < 13 ? x + 1 : 13;
    float m = -3.4e38f;
    for (int yy = y0; yy <= y1; ++yy)
        for (int xx = x0; xx <= x1; ++xx)
            m = fmaxf(m, hp[yy * 14 + xx]);
    outT[(size_t)k * 16 + b] = m;
}

// ---------------- transpose x slices into (T, K0PAD, 16), zero-padded ----------------
__global__ void xT_k(const float* __restrict__ x, float* __restrict__ xT) {
    int idx = blockIdx.x * 256 + threadIdx.x;
    if (idx >= TT * K0PAD * BB) return;
    int b = idx & 15;
    int r = idx >> 4;
    int k = r % K0PAD, t = r / K0PAD;
    float v = 0.f;
    if (k < K0) v = x[((size_t)b * TT + t) * K0 + k];
    xT[idx] = v;
}

__global__ void zero_k(float* p, int n) {
    int i = blockIdx.x * 256 + threadIdx.x;
    if (i < n) p[i] = 0.f;
}

// ---------------- fc1: out1[b][j] = relu(sum_k fc1_w[j][k]*relu(h2[b][k]) + b[j]) ----------------
__global__ void __launch_bounds__(256) fc1_k(const float* __restrict__ h2,
                                             const float* __restrict__ w,
                                             const float* __restrict__ bias,
                                             float* __restrict__ out1) {
    __shared__ float red[256];
    int j = blockIdx.x, tid = threadIdx.x;
    float acc[16];
#pragma unroll
    for (int b = 0; b < 16; b++) acc[b] = 0.f;
    for (int k = tid; k < KBIG; k += 256) {
        float wv = w[(size_t)j * KBIG + k];
#pragma unroll
        for (int b = 0; b < 16; b++)
            acc[b] += wv * fmaxf(h2[(size_t)b * KBIG + k], 0.f);
    }
    for (int b = 0; b < 16; b++) {
        red[tid] = acc[b];
        __syncthreads();
        for (int sft = 128; sft; sft >>= 1) {
            if (tid < sft) red[tid] += red[tid + sft];
            __syncthreads();
        }
        if (tid == 0) out1[b * 100 + j] = fmaxf(red[0] + bias[j], 0.f);
        __syncthreads();
    }
}

__global__ void fc2_k(const float* __restrict__ p, const float* __restrict__ w,
                      const float* __restrict__ bias, float* __restrict__ out) {
    int t = threadIdx.x;
    if (t < 160) {
        int b = t / 10, j = t - b * 10;
        float a = bias[j];
        for (int k = 0; k < 100; k++) a += p[b * 100 + k] * w[j * 100 + k];
        out[b * 10 + j] = a;
    }
}

// ---------------- host orchestration ----------------
extern "C" void kernel_launch(void* const* d_in, const int* in_sizes, int n_in,
                              void* d_out, int out_size) {
    const float* x     = (const float*)d_in[0];
    const float* Wg    = (const float*)d_in[1];
    const float* bg    = (const float*)d_in[2];
    const float* Wc    = (const float*)d_in[3];
    const float* bc    = (const float*)d_in[4];
    const float* bu_w0 = (const float*)d_in[5];
    const float* bu_b0 = (const float*)d_in[6];
    const float* bu_w1 = (const float*)d_in[7];
    const float* bu_b1 = (const float*)d_in[8];
    const float* bu_w2 = (const float*)d_in[9];
    const float* bu_b2 = (const float*)d_in[10];
    const float* td_w0 = (const float*)d_in[11];
    const float* td_b0 = (const float*)d_in[12];
    const float* td_w1 = (const float*)d_in[13];
    const float* td_b1 = (const float*)d_in[14];
    const float* fc1_w = (const float*)d_in[15];
    const float* fc1_b = (const float*)d_in[16];
    const float* fc2_w = (const float*)d_in[17];
    const float* fc2_b = (const float*)d_in[18];
    float* out = (float*)d_out;

    float *hbuf, *xT, *pBU, *pTD, *bu, *td, *gates, *fc1o;
    cudaGetSymbolAddress((void**)&hbuf,  g_h);
    cudaGetSymbolAddress((void**)&xT,    g_xT);
    cudaGetSymbolAddress((void**)&pBU,   g_poolBU);
    cudaGetSymbolAddress((void**)&pTD,   g_poolTD);
    cudaGetSymbolAddress((void**)&bu,    g_bu);
    cudaGetSymbolAddress((void**)&td,    g_td);
    cudaGetSymbolAddress((void**)&gates, g_gates);
    cudaGetSymbolAddress((void**)&fc1o,  g_fc1o);

    const int SMEM_CONV = (48 * 256 + 4 * 432) * (int)sizeof(float);  // 56064 B
    cudaFuncSetAttribute(gate_k, cudaFuncAttributeMaxDynamicSharedMemorySize, SMEM_CONV);
    cudaFuncSetAttribute(cand_k, cudaFuncAttributeMaxDynamicSharedMemorySize, SMEM_CONV);

    const int hTot = 3 * 2 * BB * HID * HW;
    zero_k<<<(hTot + 255) / 256, 256>>>(hbuf, hTot);
    xT_k<<<(TT * K0PAD * BB + 255) / 256, 256>>>(x, xT);

    int cur[3] = {0, 0, 0};
    const size_t HSZ = (size_t)BB * HID * HW;
    const float* WgN[3] = {Wg, Wg + 27648, Wg + 2 * 27648};
    const float* bgN[3] = {bg, bg + 64, bg + 128};
    const float* WcN[3] = {Wc, Wc + 13824, Wc + 2 * 13824};
    const float* bcN[3] = {bc, bc + 32, bc + 64};
    const float* buW[3] = {bu_w0, bu_w1, bu_w2};
    const float* buB[3] = {bu_b0, bu_b1, bu_b2};

    dim3 gateGrid(16, 16), candGrid(16, 8);
    const int poolBlocks = (BB * KBIG + 255) / 256;
#define HPTR(n, p) (hbuf + ((size_t)(n) * 2 + (p)) * HSZ)

    for (int t = 0; t < TT + 2; t++) {
        // ---- node 0 (runs t < T) ----
        if (t < TT) {
            int hastd = (t >= 2);
            if (hastd) {
                // td uses src[1] = hidden[1] BEFORE node1's update this step
                pool_k<<<poolBlocks, 256>>>(HPTR(1, cur[1]), pTD);
                gemm_k<<<NTD / 16, 128>>>(pTD, td_w0, td_b0, td, KBIG, KBIG, NTD);
            }
            gemm_k<<<NBU / 16, 128>>>(xT + (size_t)t * K0PAD * 16, bu_w0, bu_b0,
                                      bu, K0, K0PAD, NBU);
            gate_k<<<gateGrid, 256, SMEM_CONV>>>(bu, HPTR(0, cur[0]), td,
                                                 WgN[0], bgN[0], gates, hastd);
            cand_k<<<candGrid, 256, SMEM_CONV>>>(bu, HPTR(0, cur[0]), gates,
                                                 WcN[0], bcN[0], HPTR(0, 1 - cur[0]));
            cur[0] ^= 1;
        }
        // ---- nodes 1, 2 (run t >= 1) ----
        if (t >= 1) {
            for (int node = 1; node < 3; node++) {
                // bu uses src[node-1] AFTER its update this step (sequential order)
                pool_k<<<poolBlocks, 256>>>(HPTR(node - 1, cur[node - 1]), pBU);
                gemm_k<<<NBU / 16, 128>>>(pBU, buW[node], buB[node], bu,
                                          KBIG, KBIG, NBU);
                int hastd = (node == 1 && t >= 2);
                if (hastd) {
                    // td uses src[2] = hidden[2] BEFORE node2's update this step
                    pool_k<<<poolBlocks, 256>>>(HPTR(2, cur[2]), pTD);
                    gemm_k<<<NTD / 16, 128>>>(pTD, td_w1, td_b1, td,
                                              KBIG, KBIG, NTD);
                }
                gate_k<<<gateGrid, 256, SMEM_CONV>>>(bu, HPTR(node, cur[node]), td,
                                                     WgN[node], bgN[node], gates, hastd);
                cand_k<<<candGrid, 256, SMEM_CONV>>>(bu, HPTR(node, cur[node]), gates,
                                                     WcN[node], bcN[node],
                                                     HPTR(node, 1 - cur[node]));
                cur[node] ^= 1;
            }
        }
    }
    fc1_k<<<100, 256>>>(HPTR(2, cur[2]), fc1_w, fc1_b, fc1o);
    fc2_k<<<1, 192>>>(fc1o, fc2_w, fc2_b, out);
#undef HPTR
}

// round 4
// speedup vs baseline: 1.0161x; 1.0161x over previous
#include <cuda_runtime.h>
#include <math.h>

// ---------------- problem constants ----------------
#define BB 16
#define TT 8
#define CIN 3
#define HW 196
#define HID 32
#define IND 16
#define KBIG 6272       // HID*HW
#define K0 588          // CIN*HW
#define K0PAD 640
#define NBU 3136        // IND*HW
#define NTD 9408        // (IND+HID)*HW
#define TK 512          // GEMM K tile
#define SROW 20         // smem row stride (floats) -> conflict-free LDS.128

// ---------------- device scratch (no allocs allowed) ----------------
__device__ float g_h[3 * 2 * BB * HID * HW];   // hidden, double buffered
__device__ float g_xT[TT * K0PAD * BB];        // transposed+padded input slices
__device__ float g_poolBU[KBIG * BB];
__device__ float g_poolTD[KBIG * BB];
__device__ float g_bu[BB * NBU];
__device__ float g_td[BB * NTD];
__device__ float g_gates[BB * 64 * HW];
__device__ float g_fc1o[BB * 100];

// ---------------- f32x2 helpers ----------------
__device__ __forceinline__ unsigned long long pack2(float v) {
    unsigned long long r;
    asm("mov.b64 %0, {%1, %1};" : "=l"(r) : "f"(v));
    return r;
}
__device__ __forceinline__ void fma2(unsigned long long& d, unsigned long long a,
                                     unsigned long long b) {
    asm("fma.rn.f32x2 %0, %1, %2, %0;" : "+l"(d) : "l"(a), "l"(b));
}
__device__ __forceinline__ unsigned long long add2(unsigned long long a,
                                                   unsigned long long b) {
    unsigned long long r;
    asm("add.rn.f32x2 %0, %1, %2;" : "=l"(r) : "l"(a), "l"(b));
    return r;
}

// ---------------- GEMM: out[b][n] = sum_k inT[k][b]*W[n][k] + bias[n] ----------------
// inT: (Krows, 16) row-major (padded rows must be zero beyond K)
// W:   (Nout, K) row-major;  out: (16, Nout)
// 128 threads = 4 warps, 4 rows per warp -> 16 rows/block
__global__ void __launch_bounds__(128) gemm_k(
    const float* __restrict__ inT, const float* __restrict__ W,
    const float* __restrict__ bias, float* __restrict__ out,
    int K, int Krows, int Nout)
{
    __shared__ float s[TK * SROW];   // 40KB
    const int tid  = threadIdx.x;
    const int warp = tid >> 5, lane = tid & 31;
    const int row0 = blockIdx.x * 16 + warp * 4;

    unsigned long long acc[4][8];
#pragma unroll
    for (int r = 0; r < 4; r++)
#pragma unroll
        for (int j = 0; j < 8; j++) acc[r][j] = 0ull;

    const int ntiles = (Krows + TK - 1) / TK;
    for (int t = 0; t < ntiles; t++) {
        __syncthreads();
        // cooperative tile load: (TK x 16) floats, stride-20 rows in smem
#pragma unroll
        for (int i = 0; i < 16; i++) {
            int f = tid + i * 128;       // float4 index 0..2047
            int k = f >> 2, q = f & 3;
            int kg = t * TK + k;
            float4 v = make_float4(0.f, 0.f, 0.f, 0.f);
            if (kg < Krows) v = ((const float4*)inT)[(size_t)kg * 4 + q];
            *(float4*)(s + k * SROW + q * 4) = v;
        }
        __syncthreads();
        const int kb = t * TK;
#pragma unroll 4
        for (int it = 0; it < TK / 32; ++it) {
            int kl = it * 32 + lane;
            int kg = kb + kl;
            float w0 = 0.f, w1 = 0.f, w2 = 0.f, w3 = 0.f;
            if (kg < K) {
                const float* wp = W + (size_t)row0 * K + kg;
                w0 = wp[0];
                w1 = wp[K];
                w2 = wp[(size_t)2 * K];
                w3 = wp[(size_t)3 * K];
            }
            const ulonglong2* ap = (const ulonglong2*)(s + kl * SROW);
            ulonglong2 u0 = ap[0], u1 = ap[1], u2 = ap[2], u3 = ap[3];
            unsigned long long av[8] = {u0.x, u0.y, u1.x, u1.y, u2.x, u2.y, u3.x, u3.y};
            unsigned long long W2[4] = {pack2(w0), pack2(w1), pack2(w2), pack2(w3)};
#pragma unroll
            for (int r = 0; r < 4; r++)
#pragma unroll
                for (int j = 0; j < 8; j++) fma2(acc[r][j], W2[r], av[j]);
        }
    }
    // cross-lane reduction (butterfly over 32 lanes)
#pragma unroll
    for (int off = 16; off; off >>= 1)
#pragma unroll
        for (int r = 0; r < 4; r++)
#pragma unroll
            for (int j = 0; j < 8; j++)
                acc[r][j] = add2(acc[r][j],
                                 __shfl_xor_sync(0xffffffffu, acc[r][j], off));
    if (lane < 16) {
        const int b = lane, j = b >> 1;
#pragma unroll
        for (int r = 0; r < 4; r++) {
            unsigned long long v = acc[r][j];
            float f = (b & 1) ? __uint_as_float((unsigned)(v >> 32))
                              : __uint_as_float((unsigned)v);
            int n = row0 + r;
            out[(size_t)b * Nout + n] = f + bias[n];
        }
    }
}

// ---------------- gate conv: comb=[bu,h](+td) -> conv3x3 (48->64) -> sigmoid ----------------
// grid (16 batches, 16 groups of 4 outch), 256 threads
__global__ void __launch_bounds__(256) gate_k(
    const float* __restrict__ bu, const float* __restrict__ h,
    const float* __restrict__ td, const float* __restrict__ Wg,
    const float* __restrict__ bg, float* __restrict__ gates, int has_td)
{
    extern __shared__ float sm[];
    float* sc = sm;                 // 48 * 256  (16x16 zero-haloed images)
    float* sw = sm + 48 * 256;      // 4 * 432
    const int b = blockIdx.x, grp = blockIdx.y;
    const int tid = threadIdx.x;
    for (int i = tid; i < 48 * 256; i += 256) sc[i] = 0.f;
    for (int i = tid; i < 1728; i += 256) sw[i] = Wg[grp * 1728 + i];
    __syncthreads();
    for (int i = tid; i < 48 * 196; i += 256) {
        int ic = i / 196, p = i - ic * 196, y = p / 14, x = p - y * 14;
        float v = (ic < IND) ? bu[((size_t)b * IND + ic) * 196 + p]
                             : h[((size_t)b * HID + (ic - IND)) * 196 + p];
        if (has_td) v += td[((size_t)b * 48 + ic) * 196 + p];
        sc[ic * 256 + (y + 1) * 16 + (x + 1)] = v;
    }
    __syncthreads();
    if (tid < 196) {
        const int p = tid, y = p / 14, x = p - y * 14;
        float a0 = bg[grp * 4 + 0], a1 = bg[grp * 4 + 1];
        float a2 = bg[grp * 4 + 2], a3 = bg[grp * 4 + 3];
        const float* cbase = sc + y * 16 + x;
        for (int ic = 0; ic < 48; ++ic) {
            float v[9];
            const float* cb = cbase + ic * 256;
#pragma unroll
            for (int dy = 0; dy < 3; dy++)
#pragma unroll
                for (int dx = 0; dx < 3; dx++) v[dy * 3 + dx] = cb[dy * 16 + dx];
            const float* w0 = sw + ic * 9;
#pragma unroll
            for (int q = 0; q < 9; q++) {
                a0 += w0[q] * v[q];
                a1 += w0[432 + q] * v[q];
                a2 += w0[864 + q] * v[q];
                a3 += w0[1296 + q] * v[q];
            }
        }
        float* gp = gates + ((size_t)b * 64 + grp * 4) * 196 + p;
        gp[0]   = 1.f / (1.f + expf(-a0));
        gp[196] = 1.f / (1.f + expf(-a1));
        gp[392] = 1.f / (1.f + expf(-a2));
        gp[588] = 1.f / (1.f + expf(-a3));
    }
}

// ---------------- cand conv + GRU update: comb2=[bu, r*h] -> conv (48->32) -> tanh
//                  h_new = (1-z)*h + z*cand  ----------------
// grid (16 batches, 8 groups of 4 outch), 256 threads
__global__ void __launch_bounds__(256) cand_k(
    const float* __restrict__ bu, const float* __restrict__ h,
    const float* __restrict__ gates, const float* __restrict__ Wc,
    const float* __restrict__ bc, float* __restrict__ hnew)
{
    extern __shared__ float sm[];
    float* sc = sm;
    float* sw = sm + 48 * 256;
    const int b = blockIdx.x, grp = blockIdx.y;
    const int tid = threadIdx.x;
    for (int i = tid; i < 48 * 256; i += 256) sc[i] = 0.f;
    for (int i = tid; i < 1728; i += 256) sw[i] = Wc[grp * 1728 + i];
    __syncthreads();
    for (int i = tid; i < 48 * 196; i += 256) {
        int ic = i / 196, p = i - ic * 196, y = p / 14, x = p - y * 14;
        float v;
        if (ic < IND) {
            v = bu[((size_t)b * IND + ic) * 196 + p];
        } else {
            int c = ic - IND;
            v = gates[((size_t)b * 64 + c) * 196 + p] *
                h[((size_t)b * HID + c) * 196 + p];
        }
        sc[ic * 256 + (y + 1) * 16 + (x + 1)] = v;
    }
    __syncthreads();
    if (tid < 196) {
        const int p = tid, y = p / 14, x = p - y * 14;
        float a0 = bc[grp * 4 + 0], a1 = bc[grp * 4 + 1];
        float a2 = bc[grp * 4 + 2], a3 = bc[grp * 4 + 3];
        const float* cbase = sc + y * 16 + x;
        for (int ic = 0; ic < 48; ++ic) {
            float v[9];
            const float* cb = cbase + ic * 256;
#pragma unroll
            for (int dy = 0; dy < 3; dy++)
#pragma unroll
                for (int dx = 0; dx < 3; dx++) v[dy * 3 + dx] = cb[dy * 16 + dx];
            const float* w0 = sw + ic * 9;
#pragma unroll
            for (int q = 0; q < 9; q++) {
                a0 += w0[q] * v[q];
                a1 += w0[432 + q] * v[q];
                a2 += w0[864 + q] * v[q];
                a3 += w0[1296 + q] * v[q];
            }
        }
        float a[4] = {a0, a1, a2, a3};
#pragma unroll
        for (int g = 0; g < 4; g++) {
            int oc = grp * 4 + g;
            float z  = gates[((size_t)b * 64 + 32 + oc) * 196 + p];
            float ho = h[((size_t)b * HID + oc) * 196 + p];
            hnew[((size_t)b * HID + oc) * 196 + p] = (1.f - z) * ho + z * tanhf(a[g]);
        }
    }
}

// ---------------- maxpool 3x3 s1 p1 + transpose to (K,16) ----------------
__global__ void pool_k(const float* __restrict__ h, float* __restrict__ outT) {
    int idx = blockIdx.x * 256 + threadIdx.x;
    if (idx >= BB * KBIG) return;
    int b = idx & 15, k = idx >> 4;
    int c = k / 196, p = k - c * 196, y = p / 14, x = p - y * 14;
    const float* hp = h + ((size_t)b * HID + c) * 196;
    int y0 = y > 0 ? y - 1 : 0, y1 = y < 13 ? y + 1 : 13;
    int x0 = x > 0 ? x - 1 : 0, x1 = x < 13 ? x + 1 : 13;
    float m = -3.4e38f;
    for (int yy = y0; yy <= y1; ++yy)
        for (int xx = x0; xx <= x1; ++xx)
            m = fmaxf(m, hp[yy * 14 + xx]);
    outT[(size_t)k * 16 + b] = m;
}

// ---------------- transpose x slices into (T, K0PAD, 16), zero-padded ----------------
__global__ void xT_k(const float* __restrict__ x, float* __restrict__ xT) {
    int idx = blockIdx.x * 256 + threadIdx.x;
    if (idx >= TT * K0PAD * BB) return;
    int b = idx & 15;
    int r = idx >> 4;
    int k = r % K0PAD, t = r / K0PAD;
    float v = 0.f;
    if (k < K0) v = x[((size_t)b * TT + t) * K0 + k];
    xT[idx] = v;
}

__global__ void zero_k(float* p, int n) {
    int i = blockIdx.x * 256 + threadIdx.x;
    if (i < n) p[i] = 0.f;
}

// ---------------- fc1: out1[b][j] = relu(sum_k fc1_w[j][k]*relu(h2[b][k]) + b[j]) ----------------
__global__ void __launch_bounds__(256) fc1_k(const float* __restrict__ h2,
                                             const float* __restrict__ w,
                                             const float* __restrict__ bias,
                                             float* __restrict__ out1) {
    __shared__ float red[256];
    int j = blockIdx.x, tid = threadIdx.x;
    float acc[16];
#pragma unroll
    for (int b = 0; b < 16; b++) acc[b] = 0.f;
    for (int k = tid; k < KBIG; k += 256) {
        float wv = w[(size_t)j * KBIG + k];
#pragma unroll
        for (int b = 0; b < 16; b++)
            acc[b] += wv * fmaxf(h2[(size_t)b * KBIG + k], 0.f);
    }
    for (int b = 0; b < 16; b++) {
        red[tid] = acc[b];
        __syncthreads();
        for (int sft = 128; sft; sft >>= 1) {
            if (tid < sft) red[tid] += red[tid + sft];
            __syncthreads();
        }
        if (tid == 0) out1[b * 100 + j] = fmaxf(red[0] + bias[j], 0.f);
        __syncthreads();
    }
}

__global__ void fc2_k(const float* __restrict__ p, const float* __restrict__ w,
                      const float* __restrict__ bias, float* __restrict__ out) {
    int t = threadIdx.x;
    if (t < 160) {
        int b = t / 10, j = t - b * 10;
        float a = bias[j];
        for (int k = 0; k < 100; k++) a += p[b * 100 + k] * w[j * 100 + k];
        out[b * 10 + j] = a;
    }
}

// ---------------- host orchestration ----------------
extern "C" void kernel_launch(void* const* d_in, const int* in_sizes, int n_in,
                              void* d_out, int out_size) {
    const float* x     = (const float*)d_in[0];
    const float* Wg    = (const float*)d_in[1];
    const float* bg    = (const float*)d_in[2];
    const float* Wc    = (const float*)d_in[3];
    const float* bc    = (const float*)d_in[4];
    const float* bu_w0 = (const float*)d_in[5];
    const float* bu_b0 = (const float*)d_in[6];
    const float* bu_w1 = (const float*)d_in[7];
    const float* bu_b1 = (const float*)d_in[8];
    const float* bu_w2 = (const float*)d_in[9];
    const float* bu_b2 = (const float*)d_in[10];
    const float* td_w0 = (const float*)d_in[11];
    const float* td_b0 = (const float*)d_in[12];
    const float* td_w1 = (const float*)d_in[13];
    const float* td_b1 = (const float*)d_in[14];
    const float* fc1_w = (const float*)d_in[15];
    const float* fc1_b = (const float*)d_in[16];
    const float* fc2_w = (const float*)d_in[17];
    const float* fc2_b = (const float*)d_in[18];
    float* out = (float*)d_out;

    float *hbuf, *xT, *pBU, *pTD, *bu, *td, *gates, *fc1o;
    cudaGetSymbolAddress((void**)&hbuf,  g_h);
    cudaGetSymbolAddress((void**)&xT,    g_xT);
    cudaGetSymbolAddress((void**)&pBU,   g_poolBU);
    cudaGetSymbolAddress((void**)&pTD,   g_poolTD);
    cudaGetSymbolAddress((void**)&bu,    g_bu);
    cudaGetSymbolAddress((void**)&td,    g_td);
    cudaGetSymbolAddress((void**)&gates, g_gates);
    cudaGetSymbolAddress((void**)&fc1o,  g_fc1o);

    const int SMEM_CONV = (48 * 256 + 4 * 432) * (int)sizeof(float);  // 56064 B
    cudaFuncSetAttribute(gate_k, cudaFuncAttributeMaxDynamicSharedMemorySize, SMEM_CONV);
    cudaFuncSetAttribute(cand_k, cudaFuncAttributeMaxDynamicSharedMemorySize, SMEM_CONV);

    const int hTot = 3 * 2 * BB * HID * HW;
    zero_k<<<(hTot + 255) / 256, 256>>>(hbuf, hTot);
    xT_k<<<(TT * K0PAD * BB + 255) / 256, 256>>>(x, xT);

    int cur[3] = {0, 0, 0};
    const size_t HSZ = (size_t)BB * HID * HW;
    const float* WgN[3] = {Wg, Wg + 27648, Wg + 2 * 27648};
    const float* bgN[3] = {bg, bg + 64, bg + 128};
    const float* WcN[3] = {Wc, Wc + 13824, Wc + 2 * 13824};
    const float* bcN[3] = {bc, bc + 32, bc + 64};
    const float* buW[3] = {bu_w0, bu_w1, bu_w2};
    const float* buB[3] = {bu_b0, bu_b1, bu_b2};

    dim3 gateGrid(16, 16), candGrid(16, 8);
    const int poolBlocks = (BB * KBIG + 255) / 256;
#define HPTR(n, p) (hbuf + ((size_t)(n) * 2 + (p)) * HSZ)

    for (int t = 0; t < TT + 2; t++) {
        // ---- node 0 (runs t < T) ----
        if (t < TT) {
            int hastd = (t >= 2);
            if (hastd) {
                // td uses src[1] = hidden[1] BEFORE node1's update this step
                pool_k<<<poolBlocks, 256>>>(HPTR(1, cur[1]), pTD);
                gemm_k<<<NTD / 16, 128>>>(pTD, td_w0, td_b0, td, KBIG, KBIG, NTD);
            }
            gemm_k<<<NBU / 16, 128>>>(xT + (size_t)t * K0PAD * 16, bu_w0, bu_b0,
                                      bu, K0, K0PAD, NBU);
            gate_k<<<gateGrid, 256, SMEM_CONV>>>(bu, HPTR(0, cur[0]), td,
                                                 WgN[0], bgN[0], gates, hastd);
            cand_k<<<candGrid, 256, SMEM_CONV>>>(bu, HPTR(0, cur[0]), gates,
                                                 WcN[0], bcN[0], HPTR(0, 1 - cur[0]));
            cur[0] ^= 1;
        }
        // ---- nodes 1, 2 (run t >= 1) ----
        if (t >= 1) {
            for (int node = 1; node < 3; node++) {
                // bu uses src[node-1] AFTER its update this step (sequential order)
                pool_k<<<poolBlocks, 256>>>(HPTR(node - 1, cur[node - 1]), pBU);
                gemm_k<<<NBU / 16, 128>>>(pBU, buW[node], buB[node], bu,
                                          KBIG, KBIG, NBU);
                int hastd = (node == 1 && t >= 2);
                if (hastd) {
                    // td uses src[2] = hidden[2] BEFORE node2's update this step
                    pool_k<<<poolBlocks, 256>>>(HPTR(2, cur[2]), pTD);
                    gemm_k<<<NTD / 16, 128>>>(pTD, td_w1, td_b1, td,
                                              KBIG, KBIG, NTD);
                }
                gate_k<<<gateGrid, 256, SMEM_CONV>>>(bu, HPTR(node, cur[node]), td,
                                                     WgN[node], bgN[node], gates, hastd);
                cand_k<<<candGrid, 256, SMEM_CONV>>>(bu, HPTR(node, cur[node]), gates,
                                                     WcN[node], bcN[node],
                                                     HPTR(node, 1 - cur[node]));
                cur[node] ^= 1;
            }
        }
    }
    fc1_k<<<100, 256>>>(HPTR(2, cur[2]), fc1_w, fc1_b, fc1o);
    fc2_k<<<1, 192>>>(fc1o, fc2_w, fc2_b, out);
#undef HPTR
}

// round 6
// speedup vs baseline: 1.3814x; 1.3596x over previous
#include <cuda_runtime.h>
#include <math.h>

// ---------------- problem constants ----------------
#define BB 16
#define TT 8
#define HW 196
#define HID 32
#define IND 16
#define KBIG 6272       // HID*HW
#define K0 588          // CIN*HW
#define K0PAD 640
#define NBU 3136        // IND*HW
#define NTD 9408        // (IND+HID)*HW

// ---------------- device scratch (no allocs allowed) ----------------
__device__ float g_h[3 * 2 * BB * HID * HW];   // hidden, double buffered
__device__ float g_xT[TT * K0PAD * BB];        // transposed+padded input slices
__device__ float g_poolBU[KBIG * BB];
__device__ float g_poolTD[KBIG * BB];
__device__ float g_bu[BB * NBU];
__device__ float g_td[BB * NTD];
__device__ float g_part[3 * BB * NBU];         // K-split partials
__device__ float g_gates[BB * 64 * HW];
__device__ float g_fc1o[BB * 100];

// ---------------- f32x2 helpers ----------------
__device__ __forceinline__ unsigned long long pack2(float v) {
    unsigned long long r;
    asm("mov.b64 %0, {%1, %1};" : "=l"(r) : "f"(v));
    return r;
}
__device__ __forceinline__ void fma2(unsigned long long& d, unsigned long long a,
                                     unsigned long long b) {
    asm("fma.rn.f32x2 %0, %1, %2, %0;" : "+l"(d) : "l"(a), "l"(b));
}
__device__ __forceinline__ unsigned long long add2(unsigned long long a,
                                                   unsigned long long b) {
    unsigned long long r;
    asm("add.rn.f32x2 %0, %1, %2;" : "=l"(r) : "l"(a), "l"(b));
    return r;
}

// ================= GEMM v2b: out[b][n] = sum_k inT[k][b]*W[n][k] (+bias) =================
// inT: (Krows,16) row-major, zero-padded beyond K. W: (Nout,K). 128 thr, 4 warps,
// warp owns 4 rows; lane owns k-quad [4*lane,4*lane+4) per 128-k slab:
// 4x LDG.128 weights (1-slab prefetch), 16x LDS.128 swizzled acts, 128 FFMA2.
// KS>1 -> K-split partials (reduced by reduce3_k).
__global__ void __launch_bounds__(128, 4) gemm_k(
    const float* __restrict__ inT, const float* __restrict__ W,
    const float* __restrict__ bias, float* __restrict__ out,
    float* __restrict__ part, int K, int Krows, int Nout, int KS)
{
    __shared__ float4 smem4[768 * 4];          // 48KB: 6 slabs of (128 x 16) floats
    char* smb = (char*)smem4;
    const int tid = threadIdx.x, warp = tid >> 5, lane = tid & 31;
    const int row0 = blockIdx.x * 16 + warp * 4;
    const int ks = blockIdx.y;
    const int slabs = Krows >> 7;
    const int s0 = slabs * ks / KS, s1 = slabs * (ks + 1) / KS;

    const float* Wr[4];                        // includes +4*lane
#pragma unroll
    for (int r = 0; r < 4; r++) Wr[r] = W + (size_t)(row0 + r) * K + 4 * lane;

    unsigned long long acc[4][8];
#pragma unroll
    for (int r = 0; r < 4; r++)
#pragma unroll
        for (int i = 0; i < 8; i++) acc[r][i] = 0ull;

    for (int tb = s0; tb < s1; tb += 6) {
        const int ns = min(6, s1 - tb);
        __syncthreads();
        for (int f = tid; f < ns * 512; f += 128) {
            int row = f >> 2, q = f & 3;
            float4 v = ((const float4*)inT)[((size_t)(tb * 128 + row)) * 4 + q];
            unsigned off = (unsigned)((row << 6) | (q << 4)) ^ (((row >> 2) & 7) << 4);
            *(float4*)(smb + off) = v;
        }
        __syncthreads();
        const int kbase = tb * 128;            // slab base (lane offset inside Wr)
        float4 wc[4], wn[4];
        {
            const bool ok = (kbase + 4 * lane) < K;
#pragma unroll
            for (int r = 0; r < 4; r++)
                wc[r] = ok ? *(const float4*)(Wr[r] + kbase)
                           : make_float4(0.f, 0.f, 0.f, 0.f);
        }
        for (int s = 0; s < ns; s++) {
            const int knext = kbase + (s + 1) * 128;
            if (s + 1 < ns) {
                const bool ok = (knext + 4 * lane) < K;
#pragma unroll
                for (int r = 0; r < 4; r++)
                    wn[r] = ok ? *(const float4*)(Wr[r] + knext)
                               : make_float4(0.f, 0.f, 0.f, 0.f);
            } else {
#pragma unroll
                for (int r = 0; r < 4; r++) wn[r] = make_float4(0.f, 0.f, 0.f, 0.f);
            }
#pragma unroll
            for (int j = 0; j < 4; j++) {
                const int row = s * 128 + 4 * lane + j;
                const unsigned x = ((row >> 2) & 7) << 4;
                const unsigned b0 = (unsigned)(row << 6);
                ulonglong2 u0 = *(const ulonglong2*)(smb + ((b0 | 0u) ^ x));
                ulonglong2 u1 = *(const ulonglong2*)(smb + ((b0 | 16u) ^ x));
                ulonglong2 u2 = *(const ulonglong2*)(smb + ((b0 | 32u) ^ x));
                ulonglong2 u3 = *(const ulonglong2*)(smb + ((b0 | 48u) ^ x));
                unsigned long long av[8] = {u0.x, u0.y, u1.x, u1.y,
                                            u2.x, u2.y, u3.x, u3.y};
#pragma unroll
                for (int r = 0; r < 4; r++) {
                    unsigned long long wj = pack2(((const float*)&wc[r])[j]);
#pragma unroll
                    for (int i = 0; i < 8; i++) fma2(acc[r][i], wj, av[i]);
                }
            }
#pragma unroll
            for (int r = 0; r < 4; r++) wc[r] = wn[r];
        }
    }
    // butterfly reduction over 32 lanes
#pragma unroll
    for (int off = 16; off; off >>= 1)
#pragma unroll
        for (int r = 0; r < 4; r++)
#pragma unroll
            for (int i = 0; i < 8; i++)
                acc[r][i] = add2(acc[r][i],
                                 __shfl_xor_sync(0xffffffffu, acc[r][i], off));
    if (lane < 16) {
        const int b = lane, jj = b >> 1;
#pragma unroll
        for (int r = 0; r < 4; r++) {
            unsigned long long v = acc[r][jj];
            float f = (b & 1) ? __uint_as_float((unsigned)(v >> 32))
                              : __uint_as_float((unsigned)v);
            int n = row0 + r;
            if (KS == 1) out[(size_t)b * Nout + n] = f + bias[n];
            else part[((size_t)ks * 16 + b) * Nout + n] = f;
        }
    }
}

__global__ void reduce3_k(const float* __restrict__ part,
                          const float* __restrict__ bias,
                          float* __restrict__ out, int Nout) {
    int i = blockIdx.x * 256 + threadIdx.x;
    if (i >= 16 * Nout) return;
    int n = i % Nout;
    out[i] = part[i] + part[(size_t)16 * Nout + i] +
             part[(size_t)32 * Nout + i] + bias[n];
}

// ---------------- gate conv: comb=[bu,h](+td) -> conv3x3 (48->64) -> sigmoid ----------------
__global__ void __launch_bounds__(256) gate_k(
    const float* __restrict__ bu, const float* __restrict__ h,
    const float* __restrict__ td, const float* __restrict__ Wg,
    const float* __restrict__ bg, float* __restrict__ gates, int has_td)
{
    extern __shared__ float sm[];
    float* sc = sm;                 // 48 * 256 zero-haloed 16x16 images
    float* sw = sm + 48 * 256;      // 4 * 432
    const int b = blockIdx.x, grp = blockIdx.y;
    const int tid = threadIdx.x;
    for (int i = tid; i < 48 * 256; i += 256) sc[i] = 0.f;
    for (int i = tid; i < 1728; i += 256) sw[i] = Wg[grp * 1728 + i];
    __syncthreads();
    for (int i = tid; i < 48 * 196; i += 256) {
        int ic = i / 196, p = i - ic * 196, y = p / 14, x = p - y * 14;
        float v = (ic < IND) ? bu[((size_t)b * IND + ic) * 196 + p]
                             : h[((size_t)b * HID + (ic - IND)) * 196 + p];
        if (has_td) v += td[((size_t)b * 48 + ic) * 196 + p];
        sc[ic * 256 + (y + 1) * 16 + (x + 1)] = v;
    }
    __syncthreads();
    if (tid < 196) {
        const int p = tid, y = p / 14, x = p - y * 14;
        float a0 = bg[grp * 4 + 0], a1 = bg[grp * 4 + 1];
        float a2 = bg[grp * 4 + 2], a3 = bg[grp * 4 + 3];
        const float* cbase = sc + y * 16 + x;
        for (int ic = 0; ic < 48; ++ic) {
            float v[9];
            const float* cb = cbase + ic * 256;
#pragma unroll
            for (int dy = 0; dy < 3; dy++)
#pragma unroll
                for (int dx = 0; dx < 3; dx++) v[dy * 3 + dx] = cb[dy * 16 + dx];
            const float* w0 = sw + ic * 9;
#pragma unroll
            for (int q = 0; q < 9; q++) {
                a0 += w0[q] * v[q];
                a1 += w0[432 + q] * v[q];
                a2 += w0[864 + q] * v[q];
                a3 += w0[1296 + q] * v[q];
            }
        }
        float* gp = gates + ((size_t)b * 64 + grp * 4) * 196 + p;
        gp[0]   = 1.f / (1.f + expf(-a0));
        gp[196] = 1.f / (1.f + expf(-a1));
        gp[392] = 1.f / (1.f + expf(-a2));
        gp[588] = 1.f / (1.f + expf(-a3));
    }
}

// ---------------- cand conv + GRU update ----------------
__global__ void __launch_bounds__(256) cand_k(
    const float* __restrict__ bu, const float* __restrict__ h,
    const float* __restrict__ gates, const float* __restrict__ Wc,
    const float* __restrict__ bc, float* __restrict__ hnew)
{
    extern __shared__ float sm[];
    float* sc = sm;
    float* sw = sm + 48 * 256;
    const int b = blockIdx.x, grp = blockIdx.y;
    const int tid = threadIdx.x;
    for (int i = tid; i < 48 * 256; i += 256) sc[i] = 0.f;
    for (int i = tid; i < 1728; i += 256) sw[i] = Wc[grp * 1728 + i];
    __syncthreads();
    for (int i = tid; i < 48 * 196; i += 256) {
        int ic = i / 196, p = i - ic * 196, y = p / 14, x = p - y * 14;
        float v;
        if (ic < IND) {
            v = bu[((size_t)b * IND + ic) * 196 + p];
        } else {
            int c = ic - IND;
            v = gates[((size_t)b * 64 + c) * 196 + p] *
                h[((size_t)b * HID + c) * 196 + p];
        }
        sc[ic * 256 + (y + 1) * 16 + (x + 1)] = v;
    }
    __syncthreads();
    if (tid < 196) {
        const int p = tid, y = p / 14, x = p - y * 14;
        float a0 = bc[grp * 4 + 0], a1 = bc[grp * 4 + 1];
        float a2 = bc[grp * 4 + 2], a3 = bc[grp * 4 + 3];
        const float* cbase = sc + y * 16 + x;
        for (int ic = 0; ic < 48; ++ic) {
            float v[9];
            const float* cb = cbase + ic * 256;
#pragma unroll
            for (int dy = 0; dy < 3; dy++)
#pragma unroll
                for (int dx = 0; dx < 3; dx++) v[dy * 3 + dx] = cb[dy * 16 + dx];
            const float* w0 = sw + ic * 9;
#pragma unroll
            for (int q = 0; q < 9; q++) {
                a0 += w0[q] * v[q];
                a1 += w0[432 + q] * v[q];
                a2 += w0[864 + q] * v[q];
                a3 += w0[1296 + q] * v[q];
            }
        }
        float a[4] = {a0, a1, a2, a3};
#pragma unroll
        for (int g = 0; g < 4; g++) {
            int oc = grp * 4 + g;
            float z  = gates[((size_t)b * 64 + 32 + oc) * 196 + p];
            float ho = h[((size_t)b * HID + oc) * 196 + p];
            hnew[((size_t)b * HID + oc) * 196 + p] = (1.f - z) * ho + z * tanhf(a[g]);
        }
    }
}

// ---------------- maxpool 3x3 s1 p1 + transpose to (K,16) ----------------
__global__ void pool_k(const float* __restrict__ h, float* __restrict__ outT) {
    int idx = blockIdx.x * 256 + threadIdx.x;
    if (idx >= BB * KBIG) return;
    int b = idx & 15, k = idx >> 4;
    int c = k / 196, p = k - c * 196, y = p / 14, x = p - y * 14;
    const float* hp = h + ((size_t)b * HID + c) * 196;
    int y0 = y > 0 ? y - 1 : 0, y1 = y < 13 ? y + 1 : 13;
    int x0 = x > 0 ? x - 1 : 0, x1 = x < 13 ? x + 1 : 13;
    float m = -3.4e38f;
    for (int yy = y0; yy <= y1; ++yy)
        for (int xx = x0; xx <= x1; ++xx)
            m = fmaxf(m, hp[yy * 14 + xx]);
    outT[(size_t)k * 16 + b] = m;
}

__global__ void xT_k(const float* __restrict__ x, float* __restrict__ xT) {
    int idx = blockIdx.x * 256 + threadIdx.x;
    if (idx >= TT * K0PAD * BB) return;
    int b = idx & 15;
    int r = idx >> 4;
    int k = r % K0PAD, t = r / K0PAD;
    float v = 0.f;
    if (k < K0) v = x[((size_t)b * TT + t) * K0 + k];
    xT[idx] = v;
}

__global__ void zero_k(float* p, int n) {
    int i = blockIdx.x * 256 + threadIdx.x;
    if (i < n) p[i] = 0.f;
}

// ---------------- fc tail ----------------
__global__ void __launch_bounds__(256) fc1_k(const float* __restrict__ h2,
                                             const float* __restrict__ w,
                                             const float* __restrict__ bias,
                                             float* __restrict__ out1) {
    __shared__ float red[256];
    int j = blockIdx.x, tid = threadIdx.x;
    float acc[16];
#pragma unroll
    for (int b = 0; b < 16; b++) acc[b] = 0.f;
    for (int k = tid; k < KBIG; k += 256) {
        float wv = w[(size_t)j * KBIG + k];
#pragma unroll
        for (int b = 0; b < 16; b++)
            acc[b] += wv * fmaxf(h2[(size_t)b * KBIG + k], 0.f);
    }
    for (int b = 0; b < 16; b++) {
        red[tid] = acc[b];
        __syncthreads();
        for (int sft = 128; sft; sft >>= 1) {
            if (tid < sft) red[tid] += red[tid + sft];
            __syncthreads();
        }
        if (tid == 0) out1[b * 100 + j] = fmaxf(red[0] + bias[j], 0.f);
        __syncthreads();
    }
}

__global__ void fc2_k(const float* __restrict__ p, const float* __restrict__ w,
                      const float* __restrict__ bias, float* __restrict__ out) {
    int t = threadIdx.x;
    if (t < 160) {
        int b = t / 10, j = t - b * 10;
        float a = bias[j];
        for (int k = 0; k < 100; k++) a += p[b * 100 + k] * w[j * 100 + k];
        out[b * 10 + j] = a;
    }
}

// ---------------- host orchestration ----------------
extern "C" void kernel_launch(void* const* d_in, const int* in_sizes, int n_in,
                              void* d_out, int out_size) {
    const float* x     = (const float*)d_in[0];
    const float* Wg    = (const float*)d_in[1];
    const float* bg    = (const float*)d_in[2];
    const float* Wc    = (const float*)d_in[3];
    const float* bc    = (const float*)d_in[4];
    const float* bu_w0 = (const float*)d_in[5];
    const float* bu_b0 = (const float*)d_in[6];
    const float* bu_w1 = (const float*)d_in[7];
    const float* bu_b1 = (const float*)d_in[8];
    const float* bu_w2 = (const float*)d_in[9];
    const float* bu_b2 = (const float*)d_in[10];
    const float* td_w0 = (const float*)d_in[11];
    const float* td_b0 = (const float*)d_in[12];
    const float* td_w1 = (const float*)d_in[13];
    const float* td_b1 = (const float*)d_in[14];
    const float* fc1_w = (const float*)d_in[15];
    const float* fc1_b = (const float*)d_in[16];
    const float* fc2_w = (const float*)d_in[17];
    const float* fc2_b = (const float*)d_in[18];
    float* out = (float*)d_out;

    float *hbuf, *xT, *pBU, *pTD, *bu, *td, *part, *gates, *fc1o;
    cudaGetSymbolAddress((void**)&hbuf,  g_h);
    cudaGetSymbolAddress((void**)&xT,    g_xT);
    cudaGetSymbolAddress((void**)&pBU,   g_poolBU);
    cudaGetSymbolAddress((void**)&pTD,   g_poolTD);
    cudaGetSymbolAddress((void**)&bu,    g_bu);
    cudaGetSymbolAddress((void**)&td,    g_td);
    cudaGetSymbolAddress((void**)&part,  g_part);
    cudaGetSymbolAddress((void**)&gates, g_gates);
    cudaGetSymbolAddress((void**)&fc1o,  g_fc1o);

    const int SMEM_CONV = (48 * 256 + 4 * 432) * (int)sizeof(float);  // 56064 B
    cudaFuncSetAttribute(gate_k, cudaFuncAttributeMaxDynamicSharedMemorySize, SMEM_CONV);
    cudaFuncSetAttribute(cand_k, cudaFuncAttributeMaxDynamicSharedMemorySize, SMEM_CONV);

    const int hTot = 3 * 2 * BB * HID * HW;
    zero_k<<<(hTot + 255) / 256, 256>>>(hbuf, hTot);
    xT_k<<<(TT * K0PAD * BB + 255) / 256, 256>>>(x, xT);

    int cur[3] = {0, 0, 0};
    const size_t HSZ = (size_t)BB * HID * HW;
    const float* WgN[3] = {Wg, Wg + 27648, Wg + 2 * 27648};
    const float* bgN[3] = {bg, bg + 64, bg + 128};
    const float* WcN[3] = {Wc, Wc + 13824, Wc + 2 * 13824};
    const float* bcN[3] = {bc, bc + 32, bc + 64};
    const float* buW[3] = {bu_w0, bu_w1, bu_w2};
    const float* buB[3] = {bu_b0, bu_b1, bu_b2};

    dim3 gateGrid(16, 16), candGrid(16, 8);
    const int poolBlocks = (BB * KBIG + 255) / 256;
    const int redBlocks  = (16 * NBU + 255) / 256;
#define HPTR(n, p) (hbuf + ((size_t)(n) * 2 + (p)) * HSZ)

    for (int t = 0; t < TT + 2; t++) {
        // ---- node 0 (runs t < T) ----
        if (t < TT) {
            int hastd = (t >= 2);
            if (hastd) {
                pool_k<<<poolBlocks, 256>>>(HPTR(1, cur[1]), pTD);
                gemm_k<<<dim3(NTD / 16, 1), 128>>>(pTD, td_w0, td_b0, td, part,
                                                   KBIG, KBIG, NTD, 1);
            }
            gemm_k<<<dim3(NBU / 16, 1), 128>>>(xT + (size_t)t * K0PAD * 16, bu_w0,
                                               bu_b0, bu, part, K0, K0PAD, NBU, 1);
            gate_k<<<gateGrid, 256, SMEM_CONV>>>(bu, HPTR(0, cur[0]), td,
                                                 WgN[0], bgN[0], gates, hastd);
            cand_k<<<candGrid, 256, SMEM_CONV>>>(bu, HPTR(0, cur[0]), gates,
                                                 WcN[0], bcN[0], HPTR(0, 1 - cur[0]));
            cur[0] ^= 1;
        }
        // ---- nodes 1, 2 (run t >= 1) ----
        if (t >= 1) {
            for (int node = 1; node < 3; node++) {
                pool_k<<<poolBlocks, 256>>>(HPTR(node - 1, cur[node - 1]), pBU);
                gemm_k<<<dim3(NBU / 16, 3), 128>>>(pBU, buW[node], buB[node], bu,
                                                   part, KBIG, KBIG, NBU, 3);
                reduce3_k<<<redBlocks, 256>>>(part, buB[node], bu, NBU);
                int hastd = (node == 1 && t >= 2);
                if (hastd) {
                    pool_k<<<poolBlocks, 256>>>(HPTR(2, cur[2]), pTD);
                    gemm_k<<<dim3(NTD / 16, 1), 128>>>(pTD, td_w1, td_b1, td, part,
                                                       KBIG, KBIG, NTD, 1);
                }
                gate_k<<<gateGrid, 256, SMEM_CONV>>>(bu, HPTR(node, cur[node]), td,
                                                     WgN[node], bgN[node], gates, hastd);
                cand_k<<<candGrid, 256, SMEM_CONV>>>(bu, HPTR(node, cur[node]), gates,
                                                     WcN[node], bcN[node],
                                                     HPTR(node, 1 - cur[node]));
                cur[node] ^= 1;
            }
        }
    }
    fc1_k<<<100, 256>>>(HPTR(2, cur[2]), fc1_w, fc1_b, fc1o);
    fc2_k<<<1, 192>>>(fc1o, fc2_w, fc2_b, out);
#undef HPTR
}

// round 7
// speedup vs baseline: 1.5254x; 1.1042x over previous
#include <cuda_runtime.h>
#include <math.h>

// ---------------- problem constants ----------------
#define BB 16
#define TT 8
#define HW 196
#define HID 32
#define IND 16
#define KBIG 6272       // HID*HW
#define K0 588          // CIN*HW
#define K0PAD 640
#define NBU 3136        // IND*HW
#define NTD 9408        // (IND+HID)*HW

// ---------------- device scratch (no allocs allowed) ----------------
__device__ float g_h[3 * 2 * BB * HID * HW];   // hidden, double buffered
__device__ float g_xT[TT * K0PAD * BB];        // transposed+padded input slices
__device__ float g_poolBU[KBIG * BB];
__device__ float g_poolTD[KBIG * BB];
__device__ float g_bu[BB * NBU];
__device__ float g_td[BB * NTD];
__device__ float g_part[3 * BB * NBU];         // GEMM K-split partials
__device__ float g_gates[BB * 64 * HW];
__device__ float g_gp[2 * BB * 64 * HW];       // gate conv ic-split partials
__device__ float g_cp[2 * BB * 32 * HW];       // cand conv ic-split partials
__device__ float g_fc1o[BB * 100];

// ---------------- f32x2 helpers ----------------
__device__ __forceinline__ unsigned long long pack2(float v) {
    unsigned long long r;
    asm("mov.b64 %0, {%1, %1};" : "=l"(r) : "f"(v));
    return r;
}
__device__ __forceinline__ void fma2(unsigned long long& d, unsigned long long a,
                                     unsigned long long b) {
    asm("fma.rn.f32x2 %0, %1, %2, %0;" : "+l"(d) : "l"(a), "l"(b));
}
__device__ __forceinline__ unsigned long long add2(unsigned long long a,
                                                   unsigned long long b) {
    unsigned long long r;
    asm("add.rn.f32x2 %0, %1, %2;" : "=l"(r) : "l"(a), "l"(b));
    return r;
}

// ================= GEMM v2b (unchanged from R5) =================
__global__ void __launch_bounds__(128, 4) gemm_k(
    const float* __restrict__ inT, const float* __restrict__ W,
    const float* __restrict__ bias, float* __restrict__ out,
    float* __restrict__ part, int K, int Krows, int Nout, int KS)
{
    __shared__ float4 smem4[768 * 4];          // 48KB: 6 slabs of (128 x 16) floats
    char* smb = (char*)smem4;
    const int tid = threadIdx.x, warp = tid >> 5, lane = tid & 31;
    const int row0 = blockIdx.x * 16 + warp * 4;
    const int ks = blockIdx.y;
    const int slabs = Krows >> 7;
    const int s0 = slabs * ks / KS, s1 = slabs * (ks + 1) / KS;

    const float* Wr[4];                        // includes +4*lane
#pragma unroll
    for (int r = 0; r < 4; r++) Wr[r] = W + (size_t)(row0 + r) * K + 4 * lane;

    unsigned long long acc[4][8];
#pragma unroll
    for (int r = 0; r < 4; r++)
#pragma unroll
        for (int i = 0; i < 8; i++) acc[r][i] = 0ull;

    for (int tb = s0; tb < s1; tb += 6) {
        const int ns = min(6, s1 - tb);
        __syncthreads();
        for (int f = tid; f < ns * 512; f += 128) {
            int row = f >> 2, q = f & 3;
            float4 v = ((const float4*)inT)[((size_t)(tb * 128 + row)) * 4 + q];
            unsigned off = (unsigned)((row << 6) | (q << 4)) ^ (((row >> 2) & 7) << 4);
            *(float4*)(smb + off) = v;
        }
        __syncthreads();
        const int kbase = tb * 128;
        float4 wc[4], wn[4];
        {
            const bool ok = (kbase + 4 * lane) < K;
#pragma unroll
            for (int r = 0; r < 4; r++)
                wc[r] = ok ? *(const float4*)(Wr[r] + kbase)
                           : make_float4(0.f, 0.f, 0.f, 0.f);
        }
        for (int s = 0; s < ns; s++) {
            const int knext = kbase + (s + 1) * 128;
            if (s + 1 < ns) {
                const bool ok = (knext + 4 * lane) < K;
#pragma unroll
                for (int r = 0; r < 4; r++)
                    wn[r] = ok ? *(const float4*)(Wr[r] + knext)
                               : make_float4(0.f, 0.f, 0.f, 0.f);
            } else {
#pragma unroll
                for (int r = 0; r < 4; r++) wn[r] = make_float4(0.f, 0.f, 0.f, 0.f);
            }
#pragma unroll
            for (int j = 0; j < 4; j++) {
                const int row = s * 128 + 4 * lane + j;
                const unsigned x = ((row >> 2) & 7) << 4;
                const unsigned b0 = (unsigned)(row << 6);
                ulonglong2 u0 = *(const ulonglong2*)(smb + ((b0 | 0u) ^ x));
                ulonglong2 u1 = *(const ulonglong2*)(smb + ((b0 | 16u) ^ x));
                ulonglong2 u2 = *(const ulonglong2*)(smb + ((b0 | 32u) ^ x));
                ulonglong2 u3 = *(const ulonglong2*)(smb + ((b0 | 48u) ^ x));
                unsigned long long av[8] = {u0.x, u0.y, u1.x, u1.y,
                                            u2.x, u2.y, u3.x, u3.y};
#pragma unroll
                for (int r = 0; r < 4; r++) {
                    unsigned long long wj = pack2(((const float*)&wc[r])[j]);
#pragma unroll
                    for (int i = 0; i < 8; i++) fma2(acc[r][i], wj, av[i]);
                }
            }
#pragma unroll
            for (int r = 0; r < 4; r++) wc[r] = wn[r];
        }
    }
#pragma unroll
    for (int off = 16; off; off >>= 1)
#pragma unroll
        for (int r = 0; r < 4; r++)
#pragma unroll
            for (int i = 0; i < 8; i++)
                acc[r][i] = add2(acc[r][i],
                                 __shfl_xor_sync(0xffffffffu, acc[r][i], off));
    if (lane < 16) {
        const int b = lane, jj = b >> 1;
#pragma unroll
        for (int r = 0; r < 4; r++) {
            unsigned long long v = acc[r][jj];
            float f = (b & 1) ? __uint_as_float((unsigned)(v >> 32))
                              : __uint_as_float((unsigned)v);
            int n = row0 + r;
            if (KS == 1) out[(size_t)b * Nout + n] = f + bias[n];
            else part[((size_t)ks * 16 + b) * Nout + n] = f;
        }
    }
}

__global__ void reduce3_k(const float* __restrict__ part,
                          const float* __restrict__ bias,
                          float* __restrict__ out, int Nout) {
    int i = blockIdx.x * 256 + threadIdx.x;
    if (i >= 16 * Nout) return;
    int n = i % Nout;
    out[i] = part[i] + part[(size_t)16 * Nout + i] +
             part[(size_t)32 * Nout + i] + bias[n];
}

// ================= conv v2: ic-split partial kernels =================
// Each block: one (batch, 4-outch grp, ic-half). 24 input channels staged as
// zero-haloed 16x16 images; weights transposed to [ic][q][oc4] so one LDS.128
// serves 4 output channels. Partials (no bias/activation) to gp/cp.

// gate partial: comb=[bu,h](+td), Wg slice (4 oc x 48 ic x 9)
__global__ void __launch_bounds__(224) gate_part_k(
    const float* __restrict__ bu, const float* __restrict__ h,
    const float* __restrict__ td, const float* __restrict__ Wg,
    float* __restrict__ gp, int has_td)
{
    __shared__ float sc[24 * 256];
    __shared__ float sw[24 * 36];
    const int b = blockIdx.x, grp = blockIdx.y, half = blockIdx.z;
    const int ic0 = half * 24;
    const int tid = threadIdx.x;
    for (int i = tid; i < 24 * 256; i += 224) sc[i] = 0.f;
    for (int i = tid; i < 24 * 36; i += 224) {
        int lic = i / 36, rem = i - lic * 36, q = rem >> 2, o = rem & 3;
        sw[i] = Wg[(grp * 4 + o) * 432 + (ic0 + lic) * 9 + q];
    }
    __syncthreads();
    for (int i = tid; i < 24 * 196; i += 224) {
        int lic = i / 196, p = i - lic * 196, y = p / 14, x = p - y * 14;
        int ic = ic0 + lic;
        float v = (ic < IND) ? bu[((size_t)b * IND + ic) * 196 + p]
                             : h[((size_t)b * HID + (ic - IND)) * 196 + p];
        if (has_td) v += td[((size_t)b * 48 + ic) * 196 + p];
        sc[lic * 256 + (y + 1) * 16 + (x + 1)] = v;
    }
    __syncthreads();
    if (tid < 196) {
        const int p = tid, y = p / 14, x = p - y * 14;
        float4 a = make_float4(0.f, 0.f, 0.f, 0.f);
        const float* cbase = sc + y * 16 + x;
        for (int lic = 0; lic < 24; ++lic) {
            float v[9];
            const float* cb = cbase + lic * 256;
#pragma unroll
            for (int dy = 0; dy < 3; dy++)
#pragma unroll
                for (int dx = 0; dx < 3; dx++) v[dy * 3 + dx] = cb[dy * 16 + dx];
            const float4* wq = (const float4*)(sw + lic * 36);
#pragma unroll
            for (int q = 0; q < 9; q++) {
                float4 w = wq[q];
                a.x += w.x * v[q]; a.y += w.y * v[q];
                a.z += w.z * v[q]; a.w += w.w * v[q];
            }
        }
        float* o = gp + (((size_t)half * 16 + b) * 64 + grp * 4) * 196 + p;
        o[0] = a.x; o[196] = a.y; o[392] = a.z; o[588] = a.w;
    }
}

__global__ void gate_fin_k(const float* __restrict__ gp,
                           const float* __restrict__ bg,
                           float* __restrict__ gates) {
    int i = blockIdx.x * 256 + threadIdx.x;
    if (i >= 16 * 64 * 196) return;
    int oc = (i / 196) & 63;
    float a = gp[i] + gp[(size_t)16 * 64 * 196 + i] + bg[oc];
    gates[i] = 1.f / (1.f + expf(-a));
}

// cand partial: comb2=[bu, r*h], Wc slice (4 oc x 48 ic x 9)
__global__ void __launch_bounds__(224) cand_part_k(
    const float* __restrict__ bu, const float* __restrict__ h,
    const float* __restrict__ gates, const float* __restrict__ Wc,
    float* __restrict__ cp)
{
    __shared__ float sc[24 * 256];
    __shared__ float sw[24 * 36];
    const int b = blockIdx.x, grp = blockIdx.y, half = blockIdx.z;
    const int ic0 = half * 24;
    const int tid = threadIdx.x;
    for (int i = tid; i < 24 * 256; i += 224) sc[i] = 0.f;
    for (int i = tid; i < 24 * 36; i += 224) {
        int lic = i / 36, rem = i - lic * 36, q = rem >> 2, o = rem & 3;
        sw[i] = Wc[(grp * 4 + o) * 432 + (ic0 + lic) * 9 + q];
    }
    __syncthreads();
    for (int i = tid; i < 24 * 196; i += 224) {
        int lic = i / 196, p = i - lic * 196, y = p / 14, x = p - y * 14;
        int ic = ic0 + lic;
        float v;
        if (ic < IND) {
            v = bu[((size_t)b * IND + ic) * 196 + p];
        } else {
            int c = ic - IND;
            v = gates[((size_t)b * 64 + c) * 196 + p] *
                h[((size_t)b * HID + c) * 196 + p];
        }
        sc[lic * 256 + (y + 1) * 16 + (x + 1)] = v;
    }
    __syncthreads();
    if (tid < 196) {
        const int p = tid, y = p / 14, x = p - y * 14;
        float4 a = make_float4(0.f, 0.f, 0.f, 0.f);
        const float* cbase = sc + y * 16 + x;
        for (int lic = 0; lic < 24; ++lic) {
            float v[9];
            const float* cb = cbase + lic * 256;
#pragma unroll
            for (int dy = 0; dy < 3; dy++)
#pragma unroll
                for (int dx = 0; dx < 3; dx++) v[dy * 3 + dx] = cb[dy * 16 + dx];
            const float4* wq = (const float4*)(sw + lic * 36);
#pragma unroll
            for (int q = 0; q < 9; q++) {
                float4 w = wq[q];
                a.x += w.x * v[q]; a.y += w.y * v[q];
                a.z += w.z * v[q]; a.w += w.w * v[q];
            }
        }
        float* o = cp + (((size_t)half * 16 + b) * 32 + grp * 4) * 196 + p;
        o[0] = a.x; o[196] = a.y; o[392] = a.z; o[588] = a.w;
    }
}

__global__ void cand_fin_k(const float* __restrict__ cp,
                           const float* __restrict__ bc,
                           const float* __restrict__ gates,
                           const float* __restrict__ h,
                           float* __restrict__ hnew) {
    int i = blockIdx.x * 256 + threadIdx.x;
    if (i >= 16 * 32 * 196) return;
    int p = i % 196;
    int oc = (i / 196) & 31;
    int b = i / (32 * 196);
    float a = cp[i] + cp[(size_t)16 * 32 * 196 + i] + bc[oc];
    float z = gates[((size_t)b * 64 + 32 + oc) * 196 + p];
    float ho = h[i];
    hnew[i] = (1.f - z) * ho + z * tanhf(a);
}

// ---------------- maxpool 3x3 s1 p1 + transpose to (K,16) ----------------
__global__ void pool_k(const float* __restrict__ h, float* __restrict__ outT) {
    int idx = blockIdx.x * 256 + threadIdx.x;
    if (idx >= BB * KBIG) return;
    int b = idx & 15, k = idx >> 4;
    int c = k / 196, p = k - c * 196, y = p / 14, x = p - y * 14;
    const float* hp = h + ((size_t)b * HID + c) * 196;
    int y0 = y > 0 ? y - 1 : 0, y1 = y < 13 ? y + 1 : 13;
    int x0 = x > 0 ? x - 1 : 0, x1 = x < 13 ? x + 1 : 13;
    float m = -3.4e38f;
    for (int yy = y0; yy <= y1; ++yy)
        for (int xx = x0; xx <= x1; ++xx)
            m = fmaxf(m, hp[yy * 14 + xx]);
    outT[(size_t)k * 16 + b] = m;
}

__global__ void xT_k(const float* __restrict__ x, float* __restrict__ xT) {
    int idx = blockIdx.x * 256 + threadIdx.x;
    if (idx >= TT * K0PAD * BB) return;
    int b = idx & 15;
    int r = idx >> 4;
    int k = r % K0PAD, t = r / K0PAD;
    float v = 0.f;
    if (k < K0) v = x[((size_t)b * TT + t) * K0 + k];
    xT[idx] = v;
}

__global__ void zero_k(float* p, int n) {
    int i = blockIdx.x * 256 + threadIdx.x;
    if (i < n) p[i] = 0.f;
}

// ---------------- fc tail ----------------
__global__ void __launch_bounds__(256) fc1_k(const float* __restrict__ h2,
                                             const float* __restrict__ w,
                                             const float* __restrict__ bias,
                                             float* __restrict__ out1) {
    __shared__ float red[256];
    int j = blockIdx.x, tid = threadIdx.x;
    float acc[16];
#pragma unroll
    for (int b = 0; b < 16; b++) acc[b] = 0.f;
    for (int k = tid; k < KBIG; k += 256) {
        float wv = w[(size_t)j * KBIG + k];
#pragma unroll
        for (int b = 0; b < 16; b++)
            acc[b] += wv * fmaxf(h2[(size_t)b * KBIG + k], 0.f);
    }
    for (int b = 0; b < 16; b++) {
        red[tid] = acc[b];
        __syncthreads();
        for (int sft = 128; sft; sft >>= 1) {
            if (tid < sft) red[tid] += red[tid + sft];
            __syncthreads();
        }
        if (tid == 0) out1[b * 100 + j] = fmaxf(red[0] + bias[j], 0.f);
        __syncthreads();
    }
}

__global__ void fc2_k(const float* __restrict__ p, const float* __restrict__ w,
                      const float* __restrict__ bias, float* __restrict__ out) {
    int t = threadIdx.x;
    if (t < 160) {
        int b = t / 10, j = t - b * 10;
        float a = bias[j];
        for (int k = 0; k < 100; k++) a += p[b * 100 + k] * w[j * 100 + k];
        out[b * 10 + j] = a;
    }
}

// ---------------- host orchestration ----------------
extern "C" void kernel_launch(void* const* d_in, const int* in_sizes, int n_in,
                              void* d_out, int out_size) {
    const float* x     = (const float*)d_in[0];
    const float* Wg    = (const float*)d_in[1];
    const float* bg    = (const float*)d_in[2];
    const float* Wc    = (const float*)d_in[3];
    const float* bc    = (const float*)d_in[4];
    const float* bu_w0 = (const float*)d_in[5];
    const float* bu_b0 = (const float*)d_in[6];
    const float* bu_w1 = (const float*)d_in[7];
    const float* bu_b1 = (const float*)d_in[8];
    const float* bu_w2 = (const float*)d_in[9];
    const float* bu_b2 = (const float*)d_in[10];
    const float* td_w0 = (const float*)d_in[11];
    const float* td_b0 = (const float*)d_in[12];
    const float* td_w1 = (const float*)d_in[13];
    const float* td_b1 = (const float*)d_in[14];
    const float* fc1_w = (const float*)d_in[15];
    const float* fc1_b = (const float*)d_in[16];
    const float* fc2_w = (const float*)d_in[17];
    const float* fc2_b = (const float*)d_in[18];
    float* out = (float*)d_out;

    float *hbuf, *xT, *pBU, *pTD, *bu, *td, *part, *gates, *gp, *cp, *fc1o;
    cudaGetSymbolAddress((void**)&hbuf,  g_h);
    cudaGetSymbolAddress((void**)&xT,    g_xT);
    cudaGetSymbolAddress((void**)&pBU,   g_poolBU);
    cudaGetSymbolAddress((void**)&pTD,   g_poolTD);
    cudaGetSymbolAddress((void**)&bu,    g_bu);
    cudaGetSymbolAddress((void**)&td,    g_td);
    cudaGetSymbolAddress((void**)&part,  g_part);
    cudaGetSymbolAddress((void**)&gates, g_gates);
    cudaGetSymbolAddress((void**)&gp,    g_gp);
    cudaGetSymbolAddress((void**)&cp,    g_cp);
    cudaGetSymbolAddress((void**)&fc1o,  g_fc1o);

    const int hTot = 3 * 2 * BB * HID * HW;
    zero_k<<<(hTot + 255) / 256, 256>>>(hbuf, hTot);
    xT_k<<<(TT * K0PAD * BB + 255) / 256, 256>>>(x, xT);

    int cur[3] = {0, 0, 0};
    const size_t HSZ = (size_t)BB * HID * HW;
    const float* WgN[3] = {Wg, Wg + 27648, Wg + 2 * 27648};
    const float* bgN[3] = {bg, bg + 64, bg + 128};
    const float* WcN[3] = {Wc, Wc + 13824, Wc + 2 * 13824};
    const float* bcN[3] = {bc, bc + 32, bc + 64};
    const float* buW[3] = {bu_w0, bu_w1, bu_w2};
    const float* buB[3] = {bu_b0, bu_b1, bu_b2};

    dim3 gateGrid(16, 16, 2), candGrid(16, 8, 2);
    const int poolBlocks = (BB * KBIG + 255) / 256;
    const int redBlocks  = (16 * NBU + 255) / 256;
    const int gFinB = (16 * 64 * 196 + 255) / 256;
    const int cFinB = (16 * 32 * 196 + 255) / 256;
#define HPTR(n, p) (hbuf + ((size_t)(n) * 2 + (p)) * HSZ)

    for (int t = 0; t < TT + 2; t++) {
        // ---- node 0 (runs t < T) ----
        if (t < TT) {
            int hastd = (t >= 2);
            if (hastd) {
                pool_k<<<poolBlocks, 256>>>(HPTR(1, cur[1]), pTD);
                gemm_k<<<dim3(NTD / 16, 1), 128>>>(pTD, td_w0, td_b0, td, part,
                                                   KBIG, KBIG, NTD, 1);
            }
            gemm_k<<<dim3(NBU / 16, 1), 128>>>(xT + (size_t)t * K0PAD * 16, bu_w0,
                                               bu_b0, bu, part, K0, K0PAD, NBU, 1);
            gate_part_k<<<gateGrid, 224>>>(bu, HPTR(0, cur[0]), td, WgN[0], gp, hastd);
            gate_fin_k<<<gFinB, 256>>>(gp, bgN[0], gates);
            cand_part_k<<<candGrid, 224>>>(bu, HPTR(0, cur[0]), gates, WcN[0], cp);
            cand_fin_k<<<cFinB, 256>>>(cp, bcN[0], gates, HPTR(0, cur[0]),
                                       HPTR(0, 1 - cur[0]));
            cur[0] ^= 1;
        }
        // ---- nodes 1, 2 (run t >= 1) ----
        if (t >= 1) {
            for (int node = 1; node < 3; node++) {
                pool_k<<<poolBlocks, 256>>>(HPTR(node - 1, cur[node - 1]), pBU);
                gemm_k<<<dim3(NBU / 16, 3), 128>>>(pBU, buW[node], buB[node], bu,
                                                   part, KBIG, KBIG, NBU, 3);
                reduce3_k<<<redBlocks, 256>>>(part, buB[node], bu, NBU);
                int hastd = (node == 1 && t >= 2);
                if (hastd) {
                    pool_k<<<poolBlocks, 256>>>(HPTR(2, cur[2]), pTD);
                    gemm_k<<<dim3(NTD / 16, 1), 128>>>(pTD, td_w1, td_b1, td, part,
                                                       KBIG, KBIG, NTD, 1);
                }
                gate_part_k<<<gateGrid, 224>>>(bu, HPTR(node, cur[node]), td,
                                               WgN[node], gp, hastd);
                gate_fin_k<<<gFinB, 256>>>(gp, bgN[node], gates);
                cand_part_k<<<candGrid, 224>>>(bu, HPTR(node, cur[node]), gates,
                                               WcN[node], cp);
                cand_fin_k<<<cFinB, 256>>>(cp, bcN[node], gates, HPTR(node, cur[node]),
                                           HPTR(node, 1 - cur[node]));
                cur[node] ^= 1;
            }
        }
    }
    fc1_k<<<100, 256>>>(HPTR(2, cur[2]), fc1_w, fc1_b, fc1o);
    fc2_k<<<1, 192>>>(fc1o, fc2_w, fc2_b, out);
#undef HPTR
}